// round 7
// baseline (speedup 1.0000x reference)
#include <cuda_runtime.h>
#include <cstdint>

#define Bc 2
#define Nc 4096
#define Tc 512
#define CAP 64

// ---------------- scratch (static device globals; no allocation) ----------------
__device__ float  g_s2c[Bc * Tc * 128];                 // s_to_c
__device__ int    g_tok[Bc * Nc];                       // token index per atom
__device__ int    g_loq[Bc * Nc];                       // lo[b][tok[atom]] per atom
__device__ int    g_zoff[Bc * Nc];                      // (b*Tc+tok[atom])*CAP per atom
__device__ float  g_cq[Bc * Nc * 16];                   // relu(c) @ W_cq.T
__device__ float  g_ck[Bc * Nc * 16];                   // relu(c) @ W_ck.T
__device__ float  g_z2pc[(size_t)Bc * Tc * CAP * 16];   // compact z2p window (4 MB)
__device__ int    g_lo[Bc * Tc];                        // key-token window start per (b,tq)
__device__ int    g_amin[Bc * Tc];
__device__ int    g_amax[Bc * Tc];
__device__ int    g_anyovf;                             // any (b,tq) window exceeded CAP?
__device__ float4 g_WfD4[196 * 128];                    // (w[2f2][ch],w,w[2f2+1][ch],w) dup pairs
__device__ float  g_Ws2cT[384 * 128];
__device__ float  g_gw[16 * 128];                       // W_z2p * ln_z_g (folded)
__device__ float  g_gsum[16];
__device__ float  g_bw[16];

// ---------------- f32x2 / bf16 helpers ----------------
__device__ __forceinline__ void fma2(unsigned long long& acc, unsigned long long a, unsigned long long b) {
    asm("fma.rn.f32x2 %0, %1, %2, %0;" : "+l"(acc) : "l"(a), "l"(b));
}
__device__ __forceinline__ float lo32(unsigned long long v) { return __uint_as_float((unsigned)(v & 0xffffffffu)); }
__device__ __forceinline__ float hi32(unsigned long long v) { return __uint_as_float((unsigned)(v >> 32)); }
__device__ __forceinline__ unsigned pkbf(float lo, float hi) {
    unsigned r;
    asm("cvt.rn.bf16x2.f32 %0, %1, %2;" : "=r"(r) : "f"(hi), "f"(lo));
    return r;
}
__device__ __forceinline__ void mma16816(float* d, unsigned a0, unsigned a1, unsigned a2, unsigned a3,
                                         unsigned b0, unsigned b1) {
    asm("mma.sync.aligned.m16n8k16.row.col.f32.bf16.bf16.f32 "
        "{%0,%1,%2,%3}, {%4,%5,%6,%7}, {%8,%9}, {%10,%11,%12,%13};"
        : "=f"(d[0]), "=f"(d[1]), "=f"(d[2]), "=f"(d[3])
        : "r"(a0), "r"(a1), "r"(a2), "r"(a3), "r"(b0), "r"(b1),
          "f"(0.f), "f"(0.f), "f"(0.f), "f"(0.f));
}

// ---------------- prep: weight tables + layernorm fold + range/flag init ----------------
__global__ void prep_kernel(const float* __restrict__ W_feat, const float* __restrict__ W_s2c,
                            const float* __restrict__ W_z2p, const float* __restrict__ ln_z_g,
                            const float* __restrict__ ln_z_b) {
    int t = blockIdx.x * blockDim.x + threadIdx.x;
    int nt = gridDim.x * blockDim.x;
    for (int i = t; i < 196 * 128; i += nt) {
        int f2 = i >> 7, ch = i & 127;
        int fi0 = 2 * f2, fi1 = fi0 + 1;
        float w0 = (fi0 < 389) ? W_feat[ch * 389 + fi0] : 0.f;
        float w1 = (fi1 < 389) ? W_feat[ch * 389 + fi1] : 0.f;
        g_WfD4[i] = make_float4(w0, w0, w1, w1);
    }
    for (int i = t; i < 384 * 128; i += nt) {
        int ch = i / 384, f = i % 384;
        g_Ws2cT[f * 128 + ch] = W_s2c[i];
    }
    for (int i = t; i < 16 * 128; i += nt) {
        g_gw[i] = W_z2p[i] * ln_z_g[i & 127];
    }
    for (int i = t; i < Bc * Tc; i += nt) { g_amin[i] = Nc; g_amax[i] = -1; }
    if (t == 0) g_anyovf = 0;
    if (t < 16) {
        float gs = 0.f, bw = 0.f;
        for (int f = 0; f < 128; f++) {
            gs += W_z2p[t * 128 + f] * ln_z_g[f];
            bw += W_z2p[t * 128 + f] * ln_z_b[f];
        }
        g_gsum[t] = gs;
        g_bw[t] = bw;
    }
}

// ---------------- token index (one-hot argmax) + per-token atom range ----------------
__global__ void tok_kernel(const float* __restrict__ a2t) {
    int warp = (blockIdx.x * blockDim.x + threadIdx.x) >> 5;
    int lane = threadIdx.x & 31;
    if (warp >= Bc * Nc) return;
    const float4* row = (const float4*)(a2t + (size_t)warp * Tc);
    int idx = 0;
#pragma unroll
    for (int i = 0; i < 4; i++) {
        float4 v = row[lane + 32 * i];
        int base = 4 * (lane + 32 * i);
        if (v.x > 0.5f) idx = base;
        if (v.y > 0.5f) idx = base + 1;
        if (v.z > 0.5f) idx = base + 2;
        if (v.w > 0.5f) idx = base + 3;
    }
#pragma unroll
    for (int o = 16; o; o >>= 1) idx = max(idx, __shfl_xor_sync(0xffffffffu, idx, o));
    if (lane == 0) {
        g_tok[warp] = idx;
        int b = warp >> 12;
        int al = warp & (Nc - 1);
        atomicMin(&g_amin[b * Tc + idx], al);
        atomicMax(&g_amax[b * Tc + idx], al);
    }
}

// ---------------- s_to_c: layernorm(s_trunk) @ W_s2c.T ----------------
__global__ void s2c_kernel(const float* __restrict__ s_trunk, const float* __restrict__ g,
                           const float* __restrict__ bta) {
    __shared__ __align__(16) float xs[384];
    __shared__ float red[8];
    int row = blockIdx.x;
    int tid = threadIdx.x;
    const float* x = s_trunk + (size_t)row * 384;
    float v0 = x[tid], v1 = x[tid + 128], v2 = x[tid + 256];
    float s = v0 + v1 + v2, s2 = v0 * v0 + v1 * v1 + v2 * v2;
#pragma unroll
    for (int o = 16; o; o >>= 1) {
        s += __shfl_xor_sync(0xffffffffu, s, o);
        s2 += __shfl_xor_sync(0xffffffffu, s2, o);
    }
    if ((tid & 31) == 0) { red[tid >> 5] = s; red[4 + (tid >> 5)] = s2; }
    __syncthreads();
    s = red[0] + red[1] + red[2] + red[3];
    s2 = red[4] + red[5] + red[6] + red[7];
    float mu = s * (1.f / 384.f);
    float var = s2 * (1.f / 384.f) - mu * mu;
    float rs = rsqrtf(var + 1e-5f);
    xs[tid]       = (v0 - mu) * rs * g[tid]       + bta[tid];
    xs[tid + 128] = (v1 - mu) * rs * g[tid + 128] + bta[tid + 128];
    xs[tid + 256] = (v2 - mu) * rs * g[tid + 256] + bta[tid + 256];
    __syncthreads();
    float acc = 0.f;
#pragma unroll 4
    for (int f = 0; f < 384; f++) acc += xs[f] * g_Ws2cT[f * 128 + tid];
    g_s2c[(size_t)row * 128 + tid] = acc;
}

// ---- c embedding + cq/ck heads: 8 atoms/block (grid 1024), atom-pair f32x2, dup weights ----
__global__ void __launch_bounds__(256) c_kernel(
        const float* __restrict__ ref_pos, const float* __restrict__ ref_charge,
        const float* __restrict__ amask, const float* __restrict__ elem,
        const float* __restrict__ chars,
        const float* __restrict__ W_cq, const float* __restrict__ W_ck) {
    // phase1: fs[392][12] (8 atoms + 4 pad, 16B-aligned rows); phase2 overlay cs[8][128]+wcs[2][16][130]
    __shared__ __align__(16) float sm[5200];
    __shared__ int ts[8];
    int tid = threadIdx.x;
    int abase = blockIdx.x * 8;

#pragma unroll
    for (int pass = 0; pass < 2; pass++) {
        int fi = tid + pass * 256;
        if (fi < 392) {
            float* row = sm + fi * 12;
#pragma unroll 4
            for (int a = 0; a < 8; a++) {
                int atom = abase + a;
                float v;
                if (fi < 3)        v = ref_pos[atom * 3 + fi];
                else if (fi == 3)  v = ref_charge[atom];
                else if (fi == 4)  v = amask[atom];
                else if (fi < 133) v = elem[(size_t)atom * 128 + (fi - 5)];
                else if (fi < 389) v = chars[(size_t)atom * 256 + (fi - 133)];
                else               v = 0.f;
                row[a] = v;
            }
        }
    }
    if (tid < 8) ts[tid] = g_tok[abase + tid];
    __syncthreads();

    int ch = tid & 127;
    int half = tid >> 7;                   // 0: atoms 0..3, 1: atoms 4..7
    const ulonglong2* wp = (const ulonglong2*)g_WfD4 + ch;
    const char* fb = (const char*)sm + half * 16;
    unsigned long long acc0 = 0, acc1 = 0;
#pragma unroll 4
    for (int f2 = 0; f2 < 196; f2++) {
        ulonglong2 ww = wp[(size_t)f2 * 128];           // dup weights fi=2f2 (.x), 2f2+1 (.y)
        const char* r0 = fb + (size_t)f2 * 96;          // fi=2f2 row (stride 48B per fi)
        ulonglong2 fa = *(const ulonglong2*)(r0);       // atom pairs of this half @ fi
        ulonglong2 fc = *(const ulonglong2*)(r0 + 48);  // @ fi+1
        fma2(acc0, fa.x, ww.x); fma2(acc1, fa.y, ww.x);
        fma2(acc0, fc.x, ww.y); fma2(acc1, fc.y, ww.y);
    }

    int bb = abase >> 12;
    const float* srow = g_s2c + (size_t)bb * Tc * 128 + ch;
    int a0 = half * 4;
    float cv0 = fmaxf(lo32(acc0) + srow[(size_t)ts[a0]     * 128], 0.f);
    float cv1 = fmaxf(hi32(acc0) + srow[(size_t)ts[a0 + 1] * 128], 0.f);
    float cv2 = fmaxf(lo32(acc1) + srow[(size_t)ts[a0 + 2] * 128], 0.f);
    float cv3 = fmaxf(hi32(acc1) + srow[(size_t)ts[a0 + 3] * 128], 0.f);
    __syncthreads();                       // done reading fs

    float* cs  = sm;                        // [8][128]
    float* wcs = sm + 1024;                 // [2][16][130]
    cs[(a0 + 0) * 128 + ch] = cv0;
    cs[(a0 + 1) * 128 + ch] = cv1;
    cs[(a0 + 2) * 128 + ch] = cv2;
    cs[(a0 + 3) * 128 + ch] = cv3;
    for (int idx = tid; idx < 2 * 16 * 128; idx += 256) {
        int which = idx >> 11, i = (idx >> 7) & 15, chh = idx & 127;
        wcs[(which * 16 + i) * 130 + chh] = which ? W_ck[i * 128 + chh] : W_cq[i * 128 + chh];
    }
    __syncthreads();

    int i = tid & 15, which = (tid >> 4) & 1, a = tid >> 5;    // one output per thread
    const unsigned long long* wr = (const unsigned long long*)(wcs + (which * 16 + i) * 130);
    const unsigned long long* cr = (const unsigned long long*)(cs + a * 128);
    unsigned long long s = 0;
#pragma unroll 16
    for (int t2 = 0; t2 < 64; t2++) fma2(s, cr[t2], wr[t2]);
    float* dst = which ? g_ck : g_cq;
    dst[(size_t)(abase + a) * 16 + i] = lo32(s) + hi32(s);
}

// ---------------- compact z_to_p: one block per (b,tq); computes lo + overflow flag ----
__global__ void z2pc_kernel(const float* __restrict__ z) {
    __shared__ __align__(16) float xs[64 * 132];
    __shared__ __align__(16) float gws[16 * 130];
    __shared__ float mus[64], rss[64], gsum_s[16], bw_s[16];
    __shared__ int lo_s;
    int tid = threadIdx.x;
    int bt = blockIdx.x;                 // b*Tc + tq

    if (tid == 0) {
        int lo = 0;
        int amx = g_amax[bt];
        if (amx >= 0) {
            int amn = g_amin[bt];
            int alo = 32 * (amn >> 5) - 48; if (alo < 0) alo = 0;
            int ahi = 32 * (amx >> 5) + 79; if (ahi > Nc - 1) ahi = Nc - 1;
            int bO = (bt >> 9) * Nc;
            lo = g_tok[bO + alo];
            int hi = g_tok[bO + ahi];
            if (hi - lo >= CAP) g_anyovf = 1;
        }
        g_lo[bt] = lo;
        lo_s = lo;
    }
    for (int i = tid; i < 2048; i += 256)
        gws[(i >> 7) * 130 + (i & 127)] = g_gw[i];
    if (tid < 16) { gsum_s[tid] = g_gsum[tid]; bw_s[tid] = g_bw[tid]; }
    __syncthreads();
    int lo = lo_s;

    {
        int r = tid >> 2, j = tid & 3;
        int tk = lo + r;
        if (tk > Tc - 1) tk = Tc - 1;
        const float4* src = (const float4*)(z + ((size_t)bt * Tc + tk) * 128) + j * 8;
        float4* dst = (float4*)(xs + r * 132) + j * 8;
        float s = 0.f, s2 = 0.f;
#pragma unroll
        for (int q = 0; q < 8; q++) {
            float4 t = src[q];
            dst[q] = t;
            s += (t.x + t.y) + (t.z + t.w);
            s2 += t.x * t.x + t.y * t.y + t.z * t.z + t.w * t.w;
        }
        s  += __shfl_xor_sync(0xffffffffu, s, 1);
        s2 += __shfl_xor_sync(0xffffffffu, s2, 1);
        s  += __shfl_xor_sync(0xffffffffu, s, 2);
        s2 += __shfl_xor_sync(0xffffffffu, s2, 2);
        if (j == 0) {
            float mu = s * (1.f / 128.f);
            float var = s2 * (1.f / 128.f) - mu * mu;
            mus[r] = mu;
            rss[r] = rsqrtf(var + 1e-5f);
        }
    }
    __syncthreads();

    int ch = tid & 15, rb = tid >> 4;
    const unsigned long long* wp = (const unsigned long long*)(gws + ch * 130);
    const unsigned long long* x0 = (const unsigned long long*)(xs + (rb * 4 + 0) * 132);
    const unsigned long long* x1 = (const unsigned long long*)(xs + (rb * 4 + 1) * 132);
    const unsigned long long* x2 = (const unsigned long long*)(xs + (rb * 4 + 2) * 132);
    const unsigned long long* x3 = (const unsigned long long*)(xs + (rb * 4 + 3) * 132);
    unsigned long long a0 = 0, a1 = 0, a2 = 0, a3 = 0;
#pragma unroll 16
    for (int f2 = 0; f2 < 64; f2++) {
        unsigned long long w = wp[f2];
        fma2(a0, x0[f2], w);
        fma2(a1, x1[f2], w);
        fma2(a2, x2[f2], w);
        fma2(a3, x3[f2], w);
    }
    float gs = gsum_s[ch], bw = bw_s[ch];
    float dots[4] = { lo32(a0) + hi32(a0), lo32(a1) + hi32(a1),
                      lo32(a2) + hi32(a2), lo32(a3) + hi32(a3) };
#pragma unroll
    for (int i = 0; i < 4; i++) {
        int r = rb * 4 + i;
        g_z2pc[((size_t)bt * CAP + r) * 16 + ch] = rss[r] * (dots[i] - mus[r] * gs) + bw;
    }
}

// ---------------- per-atom lo / z-offset tables (shortens main's gather chain) ----------
__global__ void loq_kernel() {
    int idx = blockIdx.x * blockDim.x + threadIdx.x;
    if (idx >= Bc * Nc) return;
    int b = idx >> 12;
    int t = g_tok[idx];
    int bt = (b << 9) + t;
    g_loq[idx]  = g_lo[bt];
    g_zoff[idx] = bt * CAP;
}

// ---------------- main: 1 position per thread; MLP via warp mma; straight-line ----
__global__ void __launch_bounds__(256) main_kernel(
        const float* __restrict__ ref_pos, const float* __restrict__ amask,
        const int* __restrict__ uid,
        const float* __restrict__ W_pos, const float* __restrict__ W_dist,
        const float* __restrict__ W_maskp,
        const float* __restrict__ W_m1, const float* __restrict__ W_m2,
        const float* __restrict__ W_m3,
        float* __restrict__ out) {
    __shared__ __align__(16) float sw[16 * 8];     // per-d packed (wpx,wpy,wpz,wdist,wmk,...)
    __shared__ unsigned stg[8 * 288];              // bf16 staging, stride 9 (conflict-free)
    __shared__ __align__(16) float res[8 * 640];   // f32 results, stride 20
    int tid = threadIdx.x;
    int lane = tid & 31, wid = tid >> 5;
    int g = lane >> 2, t = lane & 3;
    if (tid < 16) {
        sw[tid * 8 + 0] = W_pos[3 * tid];
        sw[tid * 8 + 1] = W_pos[3 * tid + 1];
        sw[tid * 8 + 2] = W_pos[3 * tid + 2];
        sw[tid * 8 + 3] = W_dist[tid];
        sw[tid * 8 + 4] = W_maskp[tid];
    }

    unsigned bf[3][4];
#pragma unroll
    for (int L = 0; L < 3; L++) {
        const float* W = (L == 0) ? W_m1 : (L == 1) ? W_m2 : W_m3;
        float2 w00 = *(const float2*)(W + g * 16 + 2 * t);
        float2 w01 = *(const float2*)(W + g * 16 + 2 * t + 8);
        float2 w10 = *(const float2*)(W + (g + 8) * 16 + 2 * t);
        float2 w11 = *(const float2*)(W + (g + 8) * 16 + 2 * t + 8);
        bf[L][0] = pkbf(w00.x, w00.y);
        bf[L][1] = pkbf(w01.x, w01.y);
        bf[L][2] = pkbf(w10.x, w10.y);
        bf[L][3] = pkbf(w11.x, w11.y);
    }
    __syncthreads();

    int gidx = blockIdx.x * 256 + tid;
    int hh = gidx & 127;
    int ww = (gidx >> 7) & 31;
    int kk = (gidx >> 12) & 127;
    int b  = gidx >> 19;
    int q = kk * 32 + ww;
    int bq = b * Nc + q;
    int key = kk * 32 + hh - 48;
    bool inr = (unsigned)key < (unsigned)Nc;
    int bk = b * Nc + (inr ? key : 0);

    float mq = amask[bq];
    float mk = inr ? amask[bk] : 0.f;
    int uq = uid[bq];
    int uk = uid[bk];
    float v = (mq != 0.f && mk != 0.f && uq == uk) ? 1.f : 0.f;

    float qx = ref_pos[bq * 3], qy = ref_pos[bq * 3 + 1], qz = ref_pos[bq * 3 + 2];
    float kx = 0.f, ky = 0.f, kz = 0.f;
    if (inr) { kx = ref_pos[bk * 3]; ky = ref_pos[bk * 3 + 1]; kz = ref_pos[bk * 3 + 2]; }
    float dx = kx - qx, dy = ky - qy, dz = kz - qz;
    float dn = 1.f / (1.f + dx * dx + dy * dy + dz * dz);

    float p[16];
#pragma unroll
    for (int d = 0; d < 16; d++) {
        float4 wv = *(const float4*)(sw + d * 8);
        float e = sw[d * 8 + 4];
        p[d] = v * (dx * wv.x + dy * wv.y + dz * wv.z + dn * wv.w + e);
    }
    {
        const float4* cq4 = (const float4*)(g_cq + (size_t)bq * 16);
#pragma unroll
        for (int i = 0; i < 4; i++) {
            float4 tt = cq4[i];
            p[4 * i] += tt.x; p[4 * i + 1] += tt.y; p[4 * i + 2] += tt.z; p[4 * i + 3] += tt.w;
        }
    }
    if (inr) {
        int lo = g_loq[bq];            // uniform per query
        int zoff = g_zoff[bq];         // uniform per query
        int j = g_tok[bk] - lo;        // j >= 0 guaranteed by window construction
        if (j >= CAP) j = CAP - 1;     // overflow handled exactly by fixup_kernel
        const float4* zp4 = (const float4*)(g_z2pc + (size_t)(zoff + j) * 16);
        const float4* ck4 = (const float4*)(g_ck + (size_t)bk * 16);
#pragma unroll
        for (int i = 0; i < 4; i++) {
            float4 tt = zp4[i], u = ck4[i];
            p[4 * i]     += tt.x + u.x;
            p[4 * i + 1] += tt.y + u.y;
            p[4 * i + 2] += tt.z + u.z;
            p[4 * i + 3] += tt.w + u.w;
        }
    }

    // stage relu(p) as bf16 rows: [32 rows x 9 u32] per warp (stride 9 = conflict-free)
    unsigned* h2 = stg + wid * 288;
#pragma unroll
    for (int j2 = 0; j2 < 8; j2++)
        h2[lane * 9 + j2] = pkbf(fmaxf(p[2 * j2], 0.f), fmaxf(p[2 * j2 + 1], 0.f));
    __syncwarp();

    unsigned a0[2], a1[2], a2[2], a3[2];
#pragma unroll
    for (int tt = 0; tt < 2; tt++) {
        int rt = tt * 16;
        a0[tt] = h2[(rt + g) * 9 + t];
        a1[tt] = h2[(rt + g + 8) * 9 + t];
        a2[tt] = h2[(rt + g) * 9 + t + 4];
        a3[tt] = h2[(rt + g + 8) * 9 + t + 4];
    }
    __syncwarp();

    float* wsm = res + wid * 640;
#pragma unroll
    for (int tt = 0; tt < 2; tt++) {
        unsigned u0 = a0[tt], u1 = a1[tt], u2 = a2[tt], u3 = a3[tt];
        float dlo[4], dhi[4];
#pragma unroll
        for (int L = 0; L < 3; L++) {
            mma16816(dlo, u0, u1, u2, u3, bf[L][0], bf[L][1]);
            mma16816(dhi, u0, u1, u2, u3, bf[L][2], bf[L][3]);
            if (L < 2) {
                u0 = pkbf(fmaxf(dlo[0], 0.f), fmaxf(dlo[1], 0.f));
                u1 = pkbf(fmaxf(dlo[2], 0.f), fmaxf(dlo[3], 0.f));
                u2 = pkbf(fmaxf(dhi[0], 0.f), fmaxf(dhi[1], 0.f));
                u3 = pkbf(fmaxf(dhi[2], 0.f), fmaxf(dhi[3], 0.f));
            }
        }
        int r0 = tt * 16 + g, r1 = r0 + 8;
        *(float2*)(wsm + r0 * 20 + 2 * t)     = make_float2(dlo[0], dlo[1]);
        *(float2*)(wsm + r1 * 20 + 2 * t)     = make_float2(dlo[2], dlo[3]);
        *(float2*)(wsm + r0 * 20 + 8 + 2 * t) = make_float2(dhi[0], dhi[1]);
        *(float2*)(wsm + r1 * 20 + 8 + 2 * t) = make_float2(dhi[2], dhi[3]);
    }
    __syncwarp();

    float4* o4 = (float4*)(out + (size_t)gidx * 16);
    const float4* mrow = (const float4*)(wsm + lane * 20);
#pragma unroll
    for (int i = 0; i < 4; i++) {
        float4 mi = mrow[i];
        __stcs(o4 + i, make_float4(p[4 * i] + mi.x, p[4 * i + 1] + mi.y,
                                   p[4 * i + 2] + mi.z, p[4 * i + 3] + mi.w));
    }
}

// ---------------- fixup: exact recompute of window-overflow positions (rare) ----------
__global__ void fixup_kernel(
        const float* __restrict__ ref_pos, const float* __restrict__ amask,
        const int* __restrict__ uid, const float* __restrict__ z,
        const float* __restrict__ W_pos, const float* __restrict__ W_dist,
        const float* __restrict__ W_maskp,
        const float* __restrict__ W_m1, const float* __restrict__ W_m2,
        const float* __restrict__ W_m3,
        float* __restrict__ out) {
    if (!g_anyovf) return;
    int bt = blockIdx.x;                  // b*Tc + tq
    int amx = g_amax[bt];
    if (amx < 0) return;
    int amn = g_amin[bt];
    int b = bt >> 9;
    int alo = 32 * (amn >> 5) - 48; if (alo < 0) alo = 0;
    int ahi = 32 * (amx >> 5) + 79; if (ahi > Nc - 1) ahi = Nc - 1;
    int lo = g_tok[b * Nc + alo];
    int hi = g_tok[b * Nc + ahi];
    if (hi - lo < CAP) return;            // this tq was fully handled by main

    int hh = threadIdx.x;                 // 128 threads
    for (int q = amn; q <= amx; q++) {
        int kk = q >> 5;
        int key = kk * 32 + hh - 48;
        if ((unsigned)key >= (unsigned)Nc) continue;
        int bq = b * Nc + q;
        int bk = b * Nc + key;
        int tk2 = g_tok[bk];
        if (tk2 - lo < CAP) continue;     // main's value exact

        float mq = amask[bq], mk = amask[bk];
        float vv = (mq != 0.f && mk != 0.f && uid[bq] == uid[bk]) ? 1.f : 0.f;
        float dx = ref_pos[bk * 3] - ref_pos[bq * 3];
        float dy = ref_pos[bk * 3 + 1] - ref_pos[bq * 3 + 1];
        float dz = ref_pos[bk * 3 + 2] - ref_pos[bq * 3 + 2];
        float dn = 1.f / (1.f + dx * dx + dy * dy + dz * dz);

        const float* zrow = z + ((size_t)bt * Tc + tk2) * 128;
        float s = 0.f, s2 = 0.f;
        for (int f = 0; f < 128; f++) { float x = zrow[f]; s += x; s2 += x * x; }
        float mu = s * (1.f / 128.f);
        float rs = rsqrtf(s2 * (1.f / 128.f) - mu * mu + 1e-5f);

        float p[16];
        for (int d = 0; d < 16; d++) {
            float dot = 0.f;
            for (int f = 0; f < 128; f++) dot += zrow[f] * g_gw[d * 128 + f];
            float zc = rs * (dot - mu * g_gsum[d]) + g_bw[d];
            p[d] = vv * (dx * W_pos[3 * d] + dy * W_pos[3 * d + 1] + dz * W_pos[3 * d + 2]
                         + dn * W_dist[d] + W_maskp[d])
                   + g_cq[(size_t)bq * 16 + d] + g_ck[(size_t)bk * 16 + d] + zc;
        }
        float r0[16], r1[16], r2[16];
        for (int i = 0; i < 16; i++) {
            float a = 0.f;
            for (int j = 0; j < 16; j++) a += fmaxf(p[j], 0.f) * W_m1[i * 16 + j];
            r0[i] = a;
        }
        for (int i = 0; i < 16; i++) {
            float a = 0.f;
            for (int j = 0; j < 16; j++) a += fmaxf(r0[j], 0.f) * W_m2[i * 16 + j];
            r1[i] = a;
        }
        for (int i = 0; i < 16; i++) {
            float a = 0.f;
            for (int j = 0; j < 16; j++) a += fmaxf(r1[j], 0.f) * W_m3[i * 16 + j];
            r2[i] = a;
        }
        size_t gidx = ((size_t)b << 19) | ((size_t)kk << 12) | ((size_t)(q & 31) << 7) | hh;
        float* o = out + gidx * 16;
        for (int i = 0; i < 16; i++) o[i] = p[i] + r2[i];
    }
}

// ---------------- launch ----------------
extern "C" void kernel_launch(void* const* d_in, const int* in_sizes, int n_in,
                              void* d_out, int out_size) {
    const float* ref_pos             = (const float*)d_in[0];
    const float* ref_charge          = (const float*)d_in[1];
    const float* atom_pad_mask       = (const float*)d_in[2];
    const float* ref_element         = (const float*)d_in[3];
    const float* ref_atom_name_chars = (const float*)d_in[4];
    const int*   ref_space_uid       = (const int*)  d_in[5];
    const float* atom_to_token       = (const float*)d_in[6];
    const float* s_trunk             = (const float*)d_in[7];
    const float* z                   = (const float*)d_in[8];
    const float* W_feat              = (const float*)d_in[9];
    const float* W_pos               = (const float*)d_in[10];
    const float* W_dist              = (const float*)d_in[11];
    const float* W_maskp             = (const float*)d_in[12];
    const float* ln_s_g              = (const float*)d_in[13];
    const float* ln_s_b              = (const float*)d_in[14];
    const float* W_s2c               = (const float*)d_in[15];
    const float* ln_z_g              = (const float*)d_in[16];
    const float* ln_z_b              = (const float*)d_in[17];
    const float* W_z2p               = (const float*)d_in[18];
    const float* W_cq                = (const float*)d_in[19];
    const float* W_ck                = (const float*)d_in[20];
    const float* W_m1                = (const float*)d_in[21];
    const float* W_m2                = (const float*)d_in[22];
    const float* W_m3                = (const float*)d_in[23];
    float* out = (float*)d_out;

    prep_kernel<<<64, 256>>>(W_feat, W_s2c, W_z2p, ln_z_g, ln_z_b);
    tok_kernel<<<(Bc * Nc * 32) / 256, 256>>>(atom_to_token);
    s2c_kernel<<<Bc * Tc, 128>>>(s_trunk, ln_s_g, ln_s_b);
    c_kernel<<<(Bc * Nc) / 8, 256>>>(ref_pos, ref_charge, atom_pad_mask,
                                     ref_element, ref_atom_name_chars, W_cq, W_ck);
    z2pc_kernel<<<Bc * Tc, 256>>>(z);
    loq_kernel<<<(Bc * Nc) / 256, 256>>>();
    main_kernel<<<(Bc * 128 * 32 * 128) / 256, 256>>>(ref_pos, atom_pad_mask, ref_space_uid,
                                                      W_pos, W_dist, W_maskp,
                                                      W_m1, W_m2, W_m3, out);
    fixup_kernel<<<Bc * Tc, 128>>>(ref_pos, atom_pad_mask, ref_space_uid, z,
                                   W_pos, W_dist, W_maskp, W_m1, W_m2, W_m3, out);
}

// round 8
// speedup vs baseline: 1.0641x; 1.0641x over previous
#include <cuda_runtime.h>
#include <cstdint>

#define Bc 2
#define Nc 4096
#define Tc 512
#define CAP 64

// ---------------- scratch (static device globals; no allocation) ----------------
__device__ float  g_s2c[Bc * Tc * 128];                 // s_to_c
__device__ int    g_tok[Bc * Nc];                       // token index per atom
__device__ int    g_loq[Bc * Nc];                       // lo[b][tok[atom]] per atom
__device__ int    g_zoff[Bc * Nc];                      // (b*Tc+tok[atom])*CAP per atom
__device__ float  g_cq[Bc * Nc * 16];                   // relu(c) @ W_cq.T
__device__ float  g_ck[Bc * Nc * 16];                   // relu(c) @ W_ck.T
__device__ float  g_z2pc[(size_t)Bc * Tc * CAP * 16];   // compact z2p window (4 MB)
__device__ int    g_lo[Bc * Tc];                        // key-token window start per (b,tq)
__device__ int    g_amin[Bc * Tc];
__device__ int    g_amax[Bc * Tc];
__device__ int    g_anyovf;                             // any (b,tq) window exceeded CAP?
__device__ float2 g_WfP2[196 * 128];                    // (w[2f2][ch], w[2f2+1][ch]) non-dup
__device__ float  g_Ws2cT[384 * 128];
__device__ float  g_gw[16 * 128];                       // W_z2p * ln_z_g (folded)
__device__ float  g_gsum[16];
__device__ float  g_bw[16];

// ---------------- f32x2 / bf16 helpers ----------------
__device__ __forceinline__ void fma2(unsigned long long& acc, unsigned long long a, unsigned long long b) {
    asm("fma.rn.f32x2 %0, %1, %2, %0;" : "+l"(acc) : "l"(a), "l"(b));
}
__device__ __forceinline__ unsigned long long dup2(float w) {
    unsigned long long r;
    asm("mov.b64 %0, {%1,%1};" : "=l"(r) : "f"(w));
    return r;
}
__device__ __forceinline__ float lo32(unsigned long long v) { return __uint_as_float((unsigned)(v & 0xffffffffu)); }
__device__ __forceinline__ float hi32(unsigned long long v) { return __uint_as_float((unsigned)(v >> 32)); }
__device__ __forceinline__ unsigned pkbf(float lo, float hi) {
    unsigned r;
    asm("cvt.rn.bf16x2.f32 %0, %1, %2;" : "=r"(r) : "f"(hi), "f"(lo));
    return r;
}
__device__ __forceinline__ void mma16816(float* d, unsigned a0, unsigned a1, unsigned a2, unsigned a3,
                                         unsigned b0, unsigned b1) {
    asm("mma.sync.aligned.m16n8k16.row.col.f32.bf16.bf16.f32 "
        "{%0,%1,%2,%3}, {%4,%5,%6,%7}, {%8,%9}, {%10,%11,%12,%13};"
        : "=f"(d[0]), "=f"(d[1]), "=f"(d[2]), "=f"(d[3])
        : "r"(a0), "r"(a1), "r"(a2), "r"(a3), "r"(b0), "r"(b1),
          "f"(0.f), "f"(0.f), "f"(0.f), "f"(0.f));
}

// ---------------- prep: weight tables + layernorm fold + range/flag init ----------------
__global__ void prep_kernel(const float* __restrict__ W_feat, const float* __restrict__ W_s2c,
                            const float* __restrict__ W_z2p, const float* __restrict__ ln_z_g,
                            const float* __restrict__ ln_z_b) {
    int t = blockIdx.x * blockDim.x + threadIdx.x;
    int nt = gridDim.x * blockDim.x;
    for (int i = t; i < 196 * 128; i += nt) {
        int f2 = i >> 7, ch = i & 127;
        int fi0 = 2 * f2, fi1 = fi0 + 1;
        float w0 = (fi0 < 389) ? W_feat[ch * 389 + fi0] : 0.f;
        float w1 = (fi1 < 389) ? W_feat[ch * 389 + fi1] : 0.f;
        g_WfP2[i] = make_float2(w0, w1);
    }
    for (int i = t; i < 384 * 128; i += nt) {
        int ch = i / 384, f = i % 384;
        g_Ws2cT[f * 128 + ch] = W_s2c[i];
    }
    for (int i = t; i < 16 * 128; i += nt) {
        g_gw[i] = W_z2p[i] * ln_z_g[i & 127];
    }
    for (int i = t; i < Bc * Tc; i += nt) { g_amin[i] = Nc; g_amax[i] = -1; }
    if (t == 0) g_anyovf = 0;
    if (t < 16) {
        float gs = 0.f, bw = 0.f;
        for (int f = 0; f < 128; f++) {
            gs += W_z2p[t * 128 + f] * ln_z_g[f];
            bw += W_z2p[t * 128 + f] * ln_z_b[f];
        }
        g_gsum[t] = gs;
        g_bw[t] = bw;
    }
}

// ---------------- token index (one-hot argmax) + per-token atom range ----------------
__global__ void tok_kernel(const float* __restrict__ a2t) {
    int warp = (blockIdx.x * blockDim.x + threadIdx.x) >> 5;
    int lane = threadIdx.x & 31;
    if (warp >= Bc * Nc) return;
    const float4* row = (const float4*)(a2t + (size_t)warp * Tc);
    int idx = 0;
#pragma unroll
    for (int i = 0; i < 4; i++) {
        float4 v = row[lane + 32 * i];
        int base = 4 * (lane + 32 * i);
        if (v.x > 0.5f) idx = base;
        if (v.y > 0.5f) idx = base + 1;
        if (v.z > 0.5f) idx = base + 2;
        if (v.w > 0.5f) idx = base + 3;
    }
#pragma unroll
    for (int o = 16; o; o >>= 1) idx = max(idx, __shfl_xor_sync(0xffffffffu, idx, o));
    if (lane == 0) {
        g_tok[warp] = idx;
        int b = warp >> 12;
        int al = warp & (Nc - 1);
        atomicMin(&g_amin[b * Tc + idx], al);
        atomicMax(&g_amax[b * Tc + idx], al);
    }
}

// ---------------- s_to_c: layernorm(s_trunk) @ W_s2c.T ----------------
__global__ void s2c_kernel(const float* __restrict__ s_trunk, const float* __restrict__ g,
                           const float* __restrict__ bta) {
    __shared__ __align__(16) float xs[384];
    __shared__ float red[8];
    int row = blockIdx.x;
    int tid = threadIdx.x;
    const float* x = s_trunk + (size_t)row * 384;
    float v0 = x[tid], v1 = x[tid + 128], v2 = x[tid + 256];
    float s = v0 + v1 + v2, s2 = v0 * v0 + v1 * v1 + v2 * v2;
#pragma unroll
    for (int o = 16; o; o >>= 1) {
        s += __shfl_xor_sync(0xffffffffu, s, o);
        s2 += __shfl_xor_sync(0xffffffffu, s2, o);
    }
    if ((tid & 31) == 0) { red[tid >> 5] = s; red[4 + (tid >> 5)] = s2; }
    __syncthreads();
    s = red[0] + red[1] + red[2] + red[3];
    s2 = red[4] + red[5] + red[6] + red[7];
    float mu = s * (1.f / 384.f);
    float var = s2 * (1.f / 384.f) - mu * mu;
    float rs = rsqrtf(var + 1e-5f);
    xs[tid]       = (v0 - mu) * rs * g[tid]       + bta[tid];
    xs[tid + 128] = (v1 - mu) * rs * g[tid + 128] + bta[tid + 128];
    xs[tid + 256] = (v2 - mu) * rs * g[tid + 256] + bta[tid + 256];
    __syncthreads();
    float acc = 0.f;
#pragma unroll 4
    for (int f = 0; f < 384; f++) acc += xs[f] * g_Ws2cT[f * 128 + tid];
    g_s2c[(size_t)row * 128 + tid] = acc;
}

// ---- c embedding + cq/ck heads: 8 atoms/block (grid 1024), LDG.64 weights + reg-dup ----
__global__ void __launch_bounds__(256) c_kernel(
        const float* __restrict__ ref_pos, const float* __restrict__ ref_charge,
        const float* __restrict__ amask, const float* __restrict__ elem,
        const float* __restrict__ chars,
        const float* __restrict__ W_cq, const float* __restrict__ W_ck) {
    // phase1: fs[392][12] (8 atoms + 4 pad, 16B-aligned rows); phase2 overlay cs[8][128]+wcs[2][16][130]
    __shared__ __align__(16) float sm[5200];
    __shared__ int ts[8];
    int tid = threadIdx.x;
    int abase = blockIdx.x * 8;

#pragma unroll
    for (int pass = 0; pass < 2; pass++) {
        int fi = tid + pass * 256;
        if (fi < 392) {
            float* row = sm + fi * 12;
#pragma unroll 4
            for (int a = 0; a < 8; a++) {
                int atom = abase + a;
                float v;
                if (fi < 3)        v = ref_pos[atom * 3 + fi];
                else if (fi == 3)  v = ref_charge[atom];
                else if (fi == 4)  v = amask[atom];
                else if (fi < 133) v = elem[(size_t)atom * 128 + (fi - 5)];
                else if (fi < 389) v = chars[(size_t)atom * 256 + (fi - 133)];
                else               v = 0.f;
                row[a] = v;
            }
        }
    }
    if (tid < 8) ts[tid] = g_tok[abase + tid];
    __syncthreads();

    int ch = tid & 127;
    int half = tid >> 7;                   // 0: atoms 0..3, 1: atoms 4..7
    const float2* wp = (const float2*)g_WfP2 + ch;
    const char* fb = (const char*)sm + half * 16;
    unsigned long long acc0 = 0, acc1 = 0;
#pragma unroll 8
    for (int f2 = 0; f2 < 196; f2++) {
        float2 ww = wp[(size_t)f2 * 128];               // weights fi=2f2 (.x), 2f2+1 (.y)
        unsigned long long w0d = dup2(ww.x);
        unsigned long long w1d = dup2(ww.y);
        const char* r0 = fb + (size_t)f2 * 96;          // fi=2f2 row (stride 48B per fi)
        ulonglong2 fa = *(const ulonglong2*)(r0);       // atom pairs of this half @ fi
        ulonglong2 fc = *(const ulonglong2*)(r0 + 48);  // @ fi+1
        fma2(acc0, fa.x, w0d); fma2(acc1, fa.y, w0d);
        fma2(acc0, fc.x, w1d); fma2(acc1, fc.y, w1d);
    }

    int bb = abase >> 12;
    const float* srow = g_s2c + (size_t)bb * Tc * 128 + ch;
    int a0 = half * 4;
    float cv0 = fmaxf(lo32(acc0) + srow[(size_t)ts[a0]     * 128], 0.f);
    float cv1 = fmaxf(hi32(acc0) + srow[(size_t)ts[a0 + 1] * 128], 0.f);
    float cv2 = fmaxf(lo32(acc1) + srow[(size_t)ts[a0 + 2] * 128], 0.f);
    float cv3 = fmaxf(hi32(acc1) + srow[(size_t)ts[a0 + 3] * 128], 0.f);
    __syncthreads();                       // done reading fs

    float* cs  = sm;                        // [8][128]
    float* wcs = sm + 1024;                 // [2][16][130]
    cs[(a0 + 0) * 128 + ch] = cv0;
    cs[(a0 + 1) * 128 + ch] = cv1;
    cs[(a0 + 2) * 128 + ch] = cv2;
    cs[(a0 + 3) * 128 + ch] = cv3;
    for (int idx = tid; idx < 2 * 16 * 128; idx += 256) {
        int which = idx >> 11, i = (idx >> 7) & 15, chh = idx & 127;
        wcs[(which * 16 + i) * 130 + chh] = which ? W_ck[i * 128 + chh] : W_cq[i * 128 + chh];
    }
    __syncthreads();

    int i = tid & 15, which = (tid >> 4) & 1, a = tid >> 5;    // one output per thread
    const unsigned long long* wr = (const unsigned long long*)(wcs + (which * 16 + i) * 130);
    const unsigned long long* cr = (const unsigned long long*)(cs + a * 128);
    unsigned long long s = 0;
#pragma unroll 16
    for (int t2 = 0; t2 < 64; t2++) fma2(s, cr[t2], wr[t2]);
    float* dst = which ? g_ck : g_cq;
    dst[(size_t)(abase + a) * 16 + i] = lo32(s) + hi32(s);
}

// ---------------- compact z_to_p: one block per (b,tq); computes lo + overflow flag ----
__global__ void z2pc_kernel(const float* __restrict__ z) {
    __shared__ __align__(16) float xs[64 * 132];
    __shared__ __align__(16) float gws[16 * 130];
    __shared__ float mus[64], rss[64], gsum_s[16], bw_s[16];
    __shared__ int lo_s;
    int tid = threadIdx.x;
    int bt = blockIdx.x;                 // b*Tc + tq

    if (tid == 0) {
        int lo = 0;
        int amx = g_amax[bt];
        if (amx >= 0) {
            int amn = g_amin[bt];
            int alo = 32 * (amn >> 5) - 48; if (alo < 0) alo = 0;
            int ahi = 32 * (amx >> 5) + 79; if (ahi > Nc - 1) ahi = Nc - 1;
            int bO = (bt >> 9) * Nc;
            lo = g_tok[bO + alo];
            int hi = g_tok[bO + ahi];
            if (hi - lo >= CAP) g_anyovf = 1;
        }
        g_lo[bt] = lo;
        lo_s = lo;
    }
    for (int i = tid; i < 2048; i += 256)
        gws[(i >> 7) * 130 + (i & 127)] = g_gw[i];
    if (tid < 16) { gsum_s[tid] = g_gsum[tid]; bw_s[tid] = g_bw[tid]; }
    __syncthreads();
    int lo = lo_s;

    {
        int r = tid >> 2, j = tid & 3;
        int tk = lo + r;
        if (tk > Tc - 1) tk = Tc - 1;
        const float4* src = (const float4*)(z + ((size_t)bt * Tc + tk) * 128) + j * 8;
        float4* dst = (float4*)(xs + r * 132) + j * 8;
        float s = 0.f, s2 = 0.f;
#pragma unroll
        for (int q = 0; q < 8; q++) {
            float4 t = src[q];
            dst[q] = t;
            s += (t.x + t.y) + (t.z + t.w);
            s2 += t.x * t.x + t.y * t.y + t.z * t.z + t.w * t.w;
        }
        s  += __shfl_xor_sync(0xffffffffu, s, 1);
        s2 += __shfl_xor_sync(0xffffffffu, s2, 1);
        s  += __shfl_xor_sync(0xffffffffu, s, 2);
        s2 += __shfl_xor_sync(0xffffffffu, s2, 2);
        if (j == 0) {
            float mu = s * (1.f / 128.f);
            float var = s2 * (1.f / 128.f) - mu * mu;
            mus[r] = mu;
            rss[r] = rsqrtf(var + 1e-5f);
        }
    }
    __syncthreads();

    int ch = tid & 15, rb = tid >> 4;
    const unsigned long long* wp = (const unsigned long long*)(gws + ch * 130);
    const unsigned long long* x0 = (const unsigned long long*)(xs + (rb * 4 + 0) * 132);
    const unsigned long long* x1 = (const unsigned long long*)(xs + (rb * 4 + 1) * 132);
    const unsigned long long* x2 = (const unsigned long long*)(xs + (rb * 4 + 2) * 132);
    const unsigned long long* x3 = (const unsigned long long*)(xs + (rb * 4 + 3) * 132);
    unsigned long long a0 = 0, a1 = 0, a2 = 0, a3 = 0;
#pragma unroll 16
    for (int f2 = 0; f2 < 64; f2++) {
        unsigned long long w = wp[f2];
        fma2(a0, x0[f2], w);
        fma2(a1, x1[f2], w);
        fma2(a2, x2[f2], w);
        fma2(a3, x3[f2], w);
    }
    float gs = gsum_s[ch], bw = bw_s[ch];
    float dots[4] = { lo32(a0) + hi32(a0), lo32(a1) + hi32(a1),
                      lo32(a2) + hi32(a2), lo32(a3) + hi32(a3) };
#pragma unroll
    for (int i = 0; i < 4; i++) {
        int r = rb * 4 + i;
        g_z2pc[((size_t)bt * CAP + r) * 16 + ch] = rss[r] * (dots[i] - mus[r] * gs) + bw;
    }
}

// ---------------- per-atom lo / z-offset tables (shortens main's gather chain) ----------
__global__ void loq_kernel() {
    int idx = blockIdx.x * blockDim.x + threadIdx.x;
    if (idx >= Bc * Nc) return;
    int b = idx >> 12;
    int t = g_tok[idx];
    int bt = (b << 9) + t;
    g_loq[idx]  = g_lo[bt];
    g_zoff[idx] = bt * CAP;
}

// ---------------- main: 1 position per thread; MLP via warp mma; straight-line ----
__global__ void __launch_bounds__(256) main_kernel(
        const float* __restrict__ ref_pos, const float* __restrict__ amask,
        const int* __restrict__ uid,
        const float* __restrict__ W_pos, const float* __restrict__ W_dist,
        const float* __restrict__ W_maskp,
        const float* __restrict__ W_m1, const float* __restrict__ W_m2,
        const float* __restrict__ W_m3,
        float* __restrict__ out) {
    __shared__ __align__(16) float sw[16 * 8];     // per-d packed (wpx,wpy,wpz,wdist,wmk,...)
    __shared__ unsigned stg[8 * 288];              // bf16 staging, stride 9 (conflict-free)
    __shared__ __align__(16) float res[8 * 640];   // f32 results, stride 20
    int tid = threadIdx.x;
    int lane = tid & 31, wid = tid >> 5;
    int g = lane >> 2, t = lane & 3;
    if (tid < 16) {
        sw[tid * 8 + 0] = W_pos[3 * tid];
        sw[tid * 8 + 1] = W_pos[3 * tid + 1];
        sw[tid * 8 + 2] = W_pos[3 * tid + 2];
        sw[tid * 8 + 3] = W_dist[tid];
        sw[tid * 8 + 4] = W_maskp[tid];
    }

    unsigned bf[3][4];
#pragma unroll
    for (int L = 0; L < 3; L++) {
        const float* W = (L == 0) ? W_m1 : (L == 1) ? W_m2 : W_m3;
        float2 w00 = *(const float2*)(W + g * 16 + 2 * t);
        float2 w01 = *(const float2*)(W + g * 16 + 2 * t + 8);
        float2 w10 = *(const float2*)(W + (g + 8) * 16 + 2 * t);
        float2 w11 = *(const float2*)(W + (g + 8) * 16 + 2 * t + 8);
        bf[L][0] = pkbf(w00.x, w00.y);
        bf[L][1] = pkbf(w01.x, w01.y);
        bf[L][2] = pkbf(w10.x, w10.y);
        bf[L][3] = pkbf(w11.x, w11.y);
    }
    __syncthreads();

    int gidx = blockIdx.x * 256 + tid;
    int hh = gidx & 127;
    int ww = (gidx >> 7) & 31;
    int kk = (gidx >> 12) & 127;
    int b  = gidx >> 19;
    int q = kk * 32 + ww;
    int bq = b * Nc + q;
    int key = kk * 32 + hh - 48;
    bool inr = (unsigned)key < (unsigned)Nc;
    int bk = b * Nc + (inr ? key : 0);

    float mq = amask[bq];
    float mk = inr ? amask[bk] : 0.f;
    int uq = uid[bq];
    int uk = uid[bk];
    float v = (mq != 0.f && mk != 0.f && uq == uk) ? 1.f : 0.f;

    float qx = ref_pos[bq * 3], qy = ref_pos[bq * 3 + 1], qz = ref_pos[bq * 3 + 2];
    float kx = 0.f, ky = 0.f, kz = 0.f;
    if (inr) { kx = ref_pos[bk * 3]; ky = ref_pos[bk * 3 + 1]; kz = ref_pos[bk * 3 + 2]; }
    float dx = kx - qx, dy = ky - qy, dz = kz - qz;
    float dn = 1.f / (1.f + dx * dx + dy * dy + dz * dz);

    float p[16];
#pragma unroll
    for (int d = 0; d < 16; d++) {
        float4 wv = *(const float4*)(sw + d * 8);
        float e = sw[d * 8 + 4];
        p[d] = v * (dx * wv.x + dy * wv.y + dz * wv.z + dn * wv.w + e);
    }
    {
        const float4* cq4 = (const float4*)(g_cq + (size_t)bq * 16);
#pragma unroll
        for (int i = 0; i < 4; i++) {
            float4 tt = cq4[i];
            p[4 * i] += tt.x; p[4 * i + 1] += tt.y; p[4 * i + 2] += tt.z; p[4 * i + 3] += tt.w;
        }
    }
    if (inr) {
        int lo = g_loq[bq];            // uniform per query
        int zoff = g_zoff[bq];         // uniform per query
        int j = g_tok[bk] - lo;        // j >= 0 guaranteed by window construction
        if (j >= CAP) j = CAP - 1;     // overflow handled exactly by fixup_kernel
        const float4* zp4 = (const float4*)(g_z2pc + (size_t)(zoff + j) * 16);
        const float4* ck4 = (const float4*)(g_ck + (size_t)bk * 16);
#pragma unroll
        for (int i = 0; i < 4; i++) {
            float4 tt = zp4[i], u = ck4[i];
            p[4 * i]     += tt.x + u.x;
            p[4 * i + 1] += tt.y + u.y;
            p[4 * i + 2] += tt.z + u.z;
            p[4 * i + 3] += tt.w + u.w;
        }
    }

    // stage relu(p) as bf16 rows: [32 rows x 9 u32] per warp (stride 9 = conflict-free)
    unsigned* h2 = stg + wid * 288;
#pragma unroll
    for (int j2 = 0; j2 < 8; j2++)
        h2[lane * 9 + j2] = pkbf(fmaxf(p[2 * j2], 0.f), fmaxf(p[2 * j2 + 1], 0.f));
    __syncwarp();

    unsigned a0[2], a1[2], a2[2], a3[2];
#pragma unroll
    for (int tt = 0; tt < 2; tt++) {
        int rt = tt * 16;
        a0[tt] = h2[(rt + g) * 9 + t];
        a1[tt] = h2[(rt + g + 8) * 9 + t];
        a2[tt] = h2[(rt + g) * 9 + t + 4];
        a3[tt] = h2[(rt + g + 8) * 9 + t + 4];
    }
    __syncwarp();

    float* wsm = res + wid * 640;
#pragma unroll
    for (int tt = 0; tt < 2; tt++) {
        unsigned u0 = a0[tt], u1 = a1[tt], u2 = a2[tt], u3 = a3[tt];
        float dlo[4], dhi[4];
#pragma unroll
        for (int L = 0; L < 3; L++) {
            mma16816(dlo, u0, u1, u2, u3, bf[L][0], bf[L][1]);
            mma16816(dhi, u0, u1, u2, u3, bf[L][2], bf[L][3]);
            if (L < 2) {
                u0 = pkbf(fmaxf(dlo[0], 0.f), fmaxf(dlo[1], 0.f));
                u1 = pkbf(fmaxf(dlo[2], 0.f), fmaxf(dlo[3], 0.f));
                u2 = pkbf(fmaxf(dhi[0], 0.f), fmaxf(dhi[1], 0.f));
                u3 = pkbf(fmaxf(dhi[2], 0.f), fmaxf(dhi[3], 0.f));
            }
        }
        int r0 = tt * 16 + g, r1 = r0 + 8;
        *(float2*)(wsm + r0 * 20 + 2 * t)     = make_float2(dlo[0], dlo[1]);
        *(float2*)(wsm + r1 * 20 + 2 * t)     = make_float2(dlo[2], dlo[3]);
        *(float2*)(wsm + r0 * 20 + 8 + 2 * t) = make_float2(dhi[0], dhi[1]);
        *(float2*)(wsm + r1 * 20 + 8 + 2 * t) = make_float2(dhi[2], dhi[3]);
    }
    __syncwarp();

    float4* o4 = (float4*)(out + (size_t)gidx * 16);
    const float4* mrow = (const float4*)(wsm + lane * 20);
#pragma unroll
    for (int i = 0; i < 4; i++) {
        float4 mi = mrow[i];
        __stcs(o4 + i, make_float4(p[4 * i] + mi.x, p[4 * i + 1] + mi.y,
                                   p[4 * i + 2] + mi.z, p[4 * i + 3] + mi.w));
    }
}

// ---------------- fixup: exact recompute of window-overflow positions (rare) ----------
__global__ void fixup_kernel(
        const float* __restrict__ ref_pos, const float* __restrict__ amask,
        const int* __restrict__ uid, const float* __restrict__ z,
        const float* __restrict__ W_pos, const float* __restrict__ W_dist,
        const float* __restrict__ W_maskp,
        const float* __restrict__ W_m1, const float* __restrict__ W_m2,
        const float* __restrict__ W_m3,
        float* __restrict__ out) {
    if (!g_anyovf) return;
    int bt = blockIdx.x;                  // b*Tc + tq
    int amx = g_amax[bt];
    if (amx < 0) return;
    int amn = g_amin[bt];
    int b = bt >> 9;
    int alo = 32 * (amn >> 5) - 48; if (alo < 0) alo = 0;
    int ahi = 32 * (amx >> 5) + 79; if (ahi > Nc - 1) ahi = Nc - 1;
    int lo = g_tok[b * Nc + alo];
    int hi = g_tok[b * Nc + ahi];
    if (hi - lo < CAP) return;            // this tq was fully handled by main

    int hh = threadIdx.x;                 // 128 threads
    for (int q = amn; q <= amx; q++) {
        int kk = q >> 5;
        int key = kk * 32 + hh - 48;
        if ((unsigned)key >= (unsigned)Nc) continue;
        int bq = b * Nc + q;
        int bk = b * Nc + key;
        int tk2 = g_tok[bk];
        if (tk2 - lo < CAP) continue;     // main's value exact

        float mq = amask[bq], mk = amask[bk];
        float vv = (mq != 0.f && mk != 0.f && uid[bq] == uid[bk]) ? 1.f : 0.f;
        float dx = ref_pos[bk * 3] - ref_pos[bq * 3];
        float dy = ref_pos[bk * 3 + 1] - ref_pos[bq * 3 + 1];
        float dz = ref_pos[bk * 3 + 2] - ref_pos[bq * 3 + 2];
        float dn = 1.f / (1.f + dx * dx + dy * dy + dz * dz);

        const float* zrow = z + ((size_t)bt * Tc + tk2) * 128;
        float s = 0.f, s2 = 0.f;
        for (int f = 0; f < 128; f++) { float x = zrow[f]; s += x; s2 += x * x; }
        float mu = s * (1.f / 128.f);
        float rs = rsqrtf(s2 * (1.f / 128.f) - mu * mu + 1e-5f);

        float p[16];
        for (int d = 0; d < 16; d++) {
            float dot = 0.f;
            for (int f = 0; f < 128; f++) dot += zrow[f] * g_gw[d * 128 + f];
            float zc = rs * (dot - mu * g_gsum[d]) + g_bw[d];
            p[d] = vv * (dx * W_pos[3 * d] + dy * W_pos[3 * d + 1] + dz * W_pos[3 * d + 2]
                         + dn * W_dist[d] + W_maskp[d])
                   + g_cq[(size_t)bq * 16 + d] + g_ck[(size_t)bk * 16 + d] + zc;
        }
        float r0[16], r1[16], r2[16];
        for (int i = 0; i < 16; i++) {
            float a = 0.f;
            for (int j = 0; j < 16; j++) a += fmaxf(p[j], 0.f) * W_m1[i * 16 + j];
            r0[i] = a;
        }
        for (int i = 0; i < 16; i++) {
            float a = 0.f;
            for (int j = 0; j < 16; j++) a += fmaxf(r0[j], 0.f) * W_m2[i * 16 + j];
            r1[i] = a;
        }
        for (int i = 0; i < 16; i++) {
            float a = 0.f;
            for (int j = 0; j < 16; j++) a += fmaxf(r1[j], 0.f) * W_m3[i * 16 + j];
            r2[i] = a;
        }
        size_t gidx = ((size_t)b << 19) | ((size_t)kk << 12) | ((size_t)(q & 31) << 7) | hh;
        float* o = out + gidx * 16;
        for (int i = 0; i < 16; i++) o[i] = p[i] + r2[i];
    }
}

// ---------------- launch ----------------
extern "C" void kernel_launch(void* const* d_in, const int* in_sizes, int n_in,
                              void* d_out, int out_size) {
    const float* ref_pos             = (const float*)d_in[0];
    const float* ref_charge          = (const float*)d_in[1];
    const float* atom_pad_mask       = (const float*)d_in[2];
    const float* ref_element         = (const float*)d_in[3];
    const float* ref_atom_name_chars = (const float*)d_in[4];
    const int*   ref_space_uid       = (const int*)  d_in[5];
    const float* atom_to_token       = (const float*)d_in[6];
    const float* s_trunk             = (const float*)d_in[7];
    const float* z                   = (const float*)d_in[8];
    const float* W_feat              = (const float*)d_in[9];
    const float* W_pos               = (const float*)d_in[10];
    const float* W_dist              = (const float*)d_in[11];
    const float* W_maskp             = (const float*)d_in[12];
    const float* ln_s_g              = (const float*)d_in[13];
    const float* ln_s_b              = (const float*)d_in[14];
    const float* W_s2c               = (const float*)d_in[15];
    const float* ln_z_g              = (const float*)d_in[16];
    const float* ln_z_b              = (const float*)d_in[17];
    const float* W_z2p               = (const float*)d_in[18];
    const float* W_cq                = (const float*)d_in[19];
    const float* W_ck                = (const float*)d_in[20];
    const float* W_m1                = (const float*)d_in[21];
    const float* W_m2                = (const float*)d_in[22];
    const float* W_m3                = (const float*)d_in[23];
    float* out = (float*)d_out;

    prep_kernel<<<64, 256>>>(W_feat, W_s2c, W_z2p, ln_z_g, ln_z_b);
    tok_kernel<<<(Bc * Nc * 32) / 256, 256>>>(atom_to_token);
    s2c_kernel<<<Bc * Tc, 128>>>(s_trunk, ln_s_g, ln_s_b);
    c_kernel<<<(Bc * Nc) / 8, 256>>>(ref_pos, ref_charge, atom_pad_mask,
                                     ref_element, ref_atom_name_chars, W_cq, W_ck);
    z2pc_kernel<<<Bc * Tc, 256>>>(z);
    loq_kernel<<<(Bc * Nc) / 256, 256>>>();
    main_kernel<<<(Bc * 128 * 32 * 128) / 256, 256>>>(ref_pos, atom_pad_mask, ref_space_uid,
                                                      W_pos, W_dist, W_maskp,
                                                      W_m1, W_m2, W_m3, out);
    fixup_kernel<<<Bc * Tc, 128>>>(ref_pos, atom_pad_mask, ref_space_uid, z,
                                   W_pos, W_dist, W_maskp, W_m1, W_m2, W_m3, out);
}

// round 9
// speedup vs baseline: 1.0913x; 1.0256x over previous
#include <cuda_runtime.h>
#include <cstdint>

#define Bc 2
#define Nc 4096
#define Tc 512
#define CAP 64

// ---------------- scratch (static device globals; no allocation) ----------------
__device__ float  g_s2c[Bc * Tc * 128];                 // s_to_c
__device__ int    g_tok[Bc * Nc];                       // token index per atom
__device__ float  g_cq[Bc * Nc * 16];                   // relu(c) @ W_cq.T
__device__ float  g_ck[Bc * Nc * 16];                   // relu(c) @ W_ck.T
__device__ float  g_z2pc[(size_t)Bc * Tc * CAP * 16];   // compact z2p window (4 MB)
__device__ int    g_lo[Bc * Tc];                        // key-token window start per (b,tq)
__device__ int    g_amin[Bc * Tc];
__device__ int    g_amax[Bc * Tc];
__device__ int    g_anyovf;                             // any (b,tq) window exceeded CAP?
__device__ float4 g_WfQ4[196 * 64];                     // (w[c0][f],w[c1][f],w[c0][f+1],w[c1][f+1])
__device__ float  g_Ws2cT[384 * 128];
__device__ float  g_gw[16 * 128];                       // W_z2p * ln_z_g (folded)
__device__ float  g_gsum[16];
__device__ float  g_bw[16];

// ---------------- f32x2 / bf16 helpers ----------------
__device__ __forceinline__ void fma2(unsigned long long& acc, unsigned long long a, unsigned long long b) {
    asm("fma.rn.f32x2 %0, %1, %2, %0;" : "+l"(acc) : "l"(a), "l"(b));
}
__device__ __forceinline__ unsigned long long dup2(float w) {
    unsigned long long r;
    asm("mov.b64 %0, {%1,%1};" : "=l"(r) : "f"(w));
    return r;
}
__device__ __forceinline__ float lo32(unsigned long long v) { return __uint_as_float((unsigned)(v & 0xffffffffu)); }
__device__ __forceinline__ float hi32(unsigned long long v) { return __uint_as_float((unsigned)(v >> 32)); }
__device__ __forceinline__ unsigned pkbf(float lo, float hi) {
    unsigned r;
    asm("cvt.rn.bf16x2.f32 %0, %1, %2;" : "=r"(r) : "f"(hi), "f"(lo));
    return r;
}
__device__ __forceinline__ void mma16816(float* d, unsigned a0, unsigned a1, unsigned a2, unsigned a3,
                                         unsigned b0, unsigned b1) {
    asm("mma.sync.aligned.m16n8k16.row.col.f32.bf16.bf16.f32 "
        "{%0,%1,%2,%3}, {%4,%5,%6,%7}, {%8,%9}, {%10,%11,%12,%13};"
        : "=f"(d[0]), "=f"(d[1]), "=f"(d[2]), "=f"(d[3])
        : "r"(a0), "r"(a1), "r"(a2), "r"(a3), "r"(b0), "r"(b1),
          "f"(0.f), "f"(0.f), "f"(0.f), "f"(0.f));
}

// ---------------- prep: weight tables + layernorm fold + range/flag init ----------------
__global__ void prep_kernel(const float* __restrict__ W_feat, const float* __restrict__ W_s2c,
                            const float* __restrict__ W_z2p, const float* __restrict__ ln_z_g,
                            const float* __restrict__ ln_z_b) {
    int t = blockIdx.x * blockDim.x + threadIdx.x;
    int nt = gridDim.x * blockDim.x;
    for (int i = t; i < 196 * 64; i += nt) {
        int f2 = i >> 6, chp = i & 63;
        int fi0 = 2 * f2, fi1 = fi0 + 1;
        int c0 = 2 * chp, c1 = c0 + 1;
        float wx = (fi0 < 389) ? W_feat[c0 * 389 + fi0] : 0.f;
        float wy = (fi0 < 389) ? W_feat[c1 * 389 + fi0] : 0.f;
        float wz = (fi1 < 389) ? W_feat[c0 * 389 + fi1] : 0.f;
        float ww = (fi1 < 389) ? W_feat[c1 * 389 + fi1] : 0.f;
        g_WfQ4[i] = make_float4(wx, wy, wz, ww);
    }
    for (int i = t; i < 384 * 128; i += nt) {
        int ch = i / 384, f = i % 384;
        g_Ws2cT[f * 128 + ch] = W_s2c[i];
    }
    for (int i = t; i < 16 * 128; i += nt) {
        g_gw[i] = W_z2p[i] * ln_z_g[i & 127];
    }
    for (int i = t; i < Bc * Tc; i += nt) { g_amin[i] = Nc; g_amax[i] = -1; }
    if (t == 0) g_anyovf = 0;
    if (t < 16) {
        float gs = 0.f, bw = 0.f;
        for (int f = 0; f < 128; f++) {
            gs += W_z2p[t * 128 + f] * ln_z_g[f];
            bw += W_z2p[t * 128 + f] * ln_z_b[f];
        }
        g_gsum[t] = gs;
        g_bw[t] = bw;
    }
}

// ---------------- token index (one-hot argmax) + per-token atom range ----------------
__global__ void tok_kernel(const float* __restrict__ a2t) {
    int warp = (blockIdx.x * blockDim.x + threadIdx.x) >> 5;
    int lane = threadIdx.x & 31;
    if (warp >= Bc * Nc) return;
    const float4* row = (const float4*)(a2t + (size_t)warp * Tc);
    int idx = 0;
#pragma unroll
    for (int i = 0; i < 4; i++) {
        float4 v = row[lane + 32 * i];
        int base = 4 * (lane + 32 * i);
        if (v.x > 0.5f) idx = base;
        if (v.y > 0.5f) idx = base + 1;
        if (v.z > 0.5f) idx = base + 2;
        if (v.w > 0.5f) idx = base + 3;
    }
#pragma unroll
    for (int o = 16; o; o >>= 1) idx = max(idx, __shfl_xor_sync(0xffffffffu, idx, o));
    if (lane == 0) {
        g_tok[warp] = idx;
        int b = warp >> 12;
        int al = warp & (Nc - 1);
        atomicMin(&g_amin[b * Tc + idx], al);
        atomicMax(&g_amax[b * Tc + idx], al);
    }
}

// ---------------- s_to_c: layernorm(s_trunk) @ W_s2c.T ----------------
__global__ void s2c_kernel(const float* __restrict__ s_trunk, const float* __restrict__ g,
                           const float* __restrict__ bta) {
    __shared__ __align__(16) float xs[384];
    __shared__ float red[8];
    int row = blockIdx.x;
    int tid = threadIdx.x;
    const float* x = s_trunk + (size_t)row * 384;
    float v0 = x[tid], v1 = x[tid + 128], v2 = x[tid + 256];
    float s = v0 + v1 + v2, s2 = v0 * v0 + v1 * v1 + v2 * v2;
#pragma unroll
    for (int o = 16; o; o >>= 1) {
        s += __shfl_xor_sync(0xffffffffu, s, o);
        s2 += __shfl_xor_sync(0xffffffffu, s2, o);
    }
    if ((tid & 31) == 0) { red[tid >> 5] = s; red[4 + (tid >> 5)] = s2; }
    __syncthreads();
    s = red[0] + red[1] + red[2] + red[3];
    s2 = red[4] + red[5] + red[6] + red[7];
    float mu = s * (1.f / 384.f);
    float var = s2 * (1.f / 384.f) - mu * mu;
    float rs = rsqrtf(var + 1e-5f);
    xs[tid]       = (v0 - mu) * rs * g[tid]       + bta[tid];
    xs[tid + 128] = (v1 - mu) * rs * g[tid + 128] + bta[tid + 128];
    xs[tid + 256] = (v2 - mu) * rs * g[tid + 256] + bta[tid + 256];
    __syncthreads();
    float acc = 0.f;
#pragma unroll 4
    for (int f = 0; f < 384; f++) acc += xs[f] * g_Ws2cT[f * 128 + tid];
    g_s2c[(size_t)row * 128 + tid] = acc;
}

// ---- c embedding + cq/ck heads: 16 atoms/block, 2ch x 4 atoms per thread, f32x2 ----
__global__ void __launch_bounds__(256) c_kernel(
        const float* __restrict__ ref_pos, const float* __restrict__ ref_charge,
        const float* __restrict__ amask, const float* __restrict__ elem,
        const float* __restrict__ chars,
        const float* __restrict__ W_cq, const float* __restrict__ W_ck) {
    // phase1: fs[392][20] (16 atoms + 4 pad); phase2 overlay cs[16][128] + wcs[2][16][130]
    __shared__ __align__(16) float sm[7840];
    __shared__ int ts[16];
    int tid = threadIdx.x;
    int abase = blockIdx.x * 16;

#pragma unroll
    for (int pass = 0; pass < 2; pass++) {
        int fi = tid + pass * 256;
        if (fi < 392) {
            float* row = sm + fi * 20;
#pragma unroll 4
            for (int a = 0; a < 16; a++) {
                int atom = abase + a;
                float v;
                if (fi < 3)        v = ref_pos[atom * 3 + fi];
                else if (fi == 3)  v = ref_charge[atom];
                else if (fi == 4)  v = amask[atom];
                else if (fi < 133) v = elem[(size_t)atom * 128 + (fi - 5)];
                else if (fi < 389) v = chars[(size_t)atom * 256 + (fi - 133)];
                else               v = 0.f;
                row[a] = v;
            }
        }
    }
    if (tid < 16) ts[tid] = g_tok[abase + tid];
    __syncthreads();

    int chp = tid & 63;                    // channel pair: ch0 = 2chp, ch1 = 2chp+1
    int grp = tid >> 6;                    // atom group: atoms grp*4 .. grp*4+3
    const float4* wp = (const float4*)g_WfQ4 + chp;
    const char* fb = (const char*)sm + grp * 16;
    unsigned long long a00 = 0, a01 = 0, a10 = 0, a11 = 0;  // [ch][atompair]
#pragma unroll 4
    for (int f2 = 0; f2 < 196; f2++) {
        float4 w = wp[(size_t)f2 * 64];                  // (c0@fi, c1@fi, c0@fi+1, c1@fi+1)
        unsigned long long w0a = dup2(w.x), w1a = dup2(w.y);
        unsigned long long w0b = dup2(w.z), w1b = dup2(w.w);
        const char* r0 = fb + (size_t)f2 * 160;          // fi row (stride 80B per fi)
        ulonglong2 fa = *(const ulonglong2*)(r0);        // atoms (A0,A1),(A2,A3) @ fi
        ulonglong2 fc = *(const ulonglong2*)(r0 + 80);   // @ fi+1
        fma2(a00, fa.x, w0a); fma2(a01, fa.y, w0a);
        fma2(a10, fa.x, w1a); fma2(a11, fa.y, w1a);
        fma2(a00, fc.x, w0b); fma2(a01, fc.y, w0b);
        fma2(a10, fc.x, w1b); fma2(a11, fc.y, w1b);
    }

    int bb = abase >> 12;
    const float* srow = g_s2c + (size_t)bb * Tc * 128 + 2 * chp;
    int A = grp * 4;
    float2 s0 = *(const float2*)(srow + (size_t)ts[A]     * 128);
    float2 s1 = *(const float2*)(srow + (size_t)ts[A + 1] * 128);
    float2 s2v = *(const float2*)(srow + (size_t)ts[A + 2] * 128);
    float2 s3 = *(const float2*)(srow + (size_t)ts[A + 3] * 128);
    float2 c0v = make_float2(fmaxf(lo32(a00) + s0.x, 0.f), fmaxf(lo32(a10) + s0.y, 0.f));
    float2 c1v = make_float2(fmaxf(hi32(a00) + s1.x, 0.f), fmaxf(hi32(a10) + s1.y, 0.f));
    float2 c2v = make_float2(fmaxf(lo32(a01) + s2v.x, 0.f), fmaxf(lo32(a11) + s2v.y, 0.f));
    float2 c3v = make_float2(fmaxf(hi32(a01) + s3.x, 0.f), fmaxf(hi32(a11) + s3.y, 0.f));
    __syncthreads();                       // done reading fs

    float* cs  = sm;                        // [16][128]
    float* wcs = sm + 2048;                 // [2][16][130]
    *(float2*)(cs + (A + 0) * 128 + 2 * chp) = c0v;
    *(float2*)(cs + (A + 1) * 128 + 2 * chp) = c1v;
    *(float2*)(cs + (A + 2) * 128 + 2 * chp) = c2v;
    *(float2*)(cs + (A + 3) * 128 + 2 * chp) = c3v;
    for (int idx = tid; idx < 2 * 16 * 128; idx += 256) {
        int which = idx >> 11, i = (idx >> 7) & 15, chh = idx & 127;
        wcs[(which * 16 + i) * 130 + chh] = which ? W_ck[i * 128 + chh] : W_cq[i * 128 + chh];
    }
    __syncthreads();

    int i = tid & 15, which = (tid >> 4) & 1, a = tid >> 5;    // atoms a, a+8
    const unsigned long long* wr  = (const unsigned long long*)(wcs + (which * 16 + i) * 130);
    const unsigned long long* cr0 = (const unsigned long long*)(cs + a * 128);
    const unsigned long long* cr1 = (const unsigned long long*)(cs + (a + 8) * 128);
    unsigned long long s0a = 0, s1a = 0;
#pragma unroll 16
    for (int t2 = 0; t2 < 64; t2++) {
        unsigned long long w = wr[t2];
        fma2(s0a, cr0[t2], w);
        fma2(s1a, cr1[t2], w);
    }
    float* dst = which ? g_ck : g_cq;
    dst[(size_t)(abase + a) * 16 + i]     = lo32(s0a) + hi32(s0a);
    dst[(size_t)(abase + a + 8) * 16 + i] = lo32(s1a) + hi32(s1a);
}

// ---------------- compact z_to_p: one block per (b,tq); computes lo + overflow flag ----
__global__ void z2pc_kernel(const float* __restrict__ z) {
    __shared__ __align__(16) float xs[64 * 132];
    __shared__ __align__(16) float gws[16 * 130];
    __shared__ float mus[64], rss[64], gsum_s[16], bw_s[16];
    __shared__ int lo_s;
    int tid = threadIdx.x;
    int bt = blockIdx.x;                 // b*Tc + tq

    if (tid == 0) {
        int lo = 0;
        int amx = g_amax[bt];
        if (amx >= 0) {
            int amn = g_amin[bt];
            int alo = 32 * (amn >> 5) - 48; if (alo < 0) alo = 0;
            int ahi = 32 * (amx >> 5) + 79; if (ahi > Nc - 1) ahi = Nc - 1;
            int bO = (bt >> 9) * Nc;
            lo = g_tok[bO + alo];
            int hi = g_tok[bO + ahi];
            if (hi - lo >= CAP) g_anyovf = 1;
        }
        g_lo[bt] = lo;
        lo_s = lo;
    }
    for (int i = tid; i < 2048; i += 256)
        gws[(i >> 7) * 130 + (i & 127)] = g_gw[i];
    if (tid < 16) { gsum_s[tid] = g_gsum[tid]; bw_s[tid] = g_bw[tid]; }
    __syncthreads();
    int lo = lo_s;

    {
        int r = tid >> 2, j = tid & 3;
        int tk = lo + r;
        if (tk > Tc - 1) tk = Tc - 1;
        const float4* src = (const float4*)(z + ((size_t)bt * Tc + tk) * 128) + j * 8;
        float4* dst = (float4*)(xs + r * 132) + j * 8;
        float s = 0.f, s2 = 0.f;
#pragma unroll
        for (int q = 0; q < 8; q++) {
            float4 t = src[q];
            dst[q] = t;
            s += (t.x + t.y) + (t.z + t.w);
            s2 += t.x * t.x + t.y * t.y + t.z * t.z + t.w * t.w;
        }
        s  += __shfl_xor_sync(0xffffffffu, s, 1);
        s2 += __shfl_xor_sync(0xffffffffu, s2, 1);
        s  += __shfl_xor_sync(0xffffffffu, s, 2);
        s2 += __shfl_xor_sync(0xffffffffu, s2, 2);
        if (j == 0) {
            float mu = s * (1.f / 128.f);
            float var = s2 * (1.f / 128.f) - mu * mu;
            mus[r] = mu;
            rss[r] = rsqrtf(var + 1e-5f);
        }
    }
    __syncthreads();

    int ch = tid & 15, rb = tid >> 4;
    const unsigned long long* wp = (const unsigned long long*)(gws + ch * 130);
    const unsigned long long* x0 = (const unsigned long long*)(xs + (rb * 4 + 0) * 132);
    const unsigned long long* x1 = (const unsigned long long*)(xs + (rb * 4 + 1) * 132);
    const unsigned long long* x2 = (const unsigned long long*)(xs + (rb * 4 + 2) * 132);
    const unsigned long long* x3 = (const unsigned long long*)(xs + (rb * 4 + 3) * 132);
    unsigned long long a0 = 0, a1 = 0, a2 = 0, a3 = 0;
#pragma unroll 16
    for (int f2 = 0; f2 < 64; f2++) {
        unsigned long long w = wp[f2];
        fma2(a0, x0[f2], w);
        fma2(a1, x1[f2], w);
        fma2(a2, x2[f2], w);
        fma2(a3, x3[f2], w);
    }
    float gs = gsum_s[ch], bw = bw_s[ch];
    float dots[4] = { lo32(a0) + hi32(a0), lo32(a1) + hi32(a1),
                      lo32(a2) + hi32(a2), lo32(a3) + hi32(a3) };
#pragma unroll
    for (int i = 0; i < 4; i++) {
        int r = rb * 4 + i;
        g_z2pc[((size_t)bt * CAP + r) * 16 + ch] = rss[r] * (dots[i] - mus[r] * gs) + bw;
    }
}

// ---------------- main: 1 position per thread; MLP via warp mma; straight-line ----
__global__ void __launch_bounds__(256) main_kernel(
        const float* __restrict__ ref_pos, const float* __restrict__ amask,
        const int* __restrict__ uid,
        const float* __restrict__ W_pos, const float* __restrict__ W_dist,
        const float* __restrict__ W_maskp,
        const float* __restrict__ W_m1, const float* __restrict__ W_m2,
        const float* __restrict__ W_m3,
        float* __restrict__ out) {
    __shared__ __align__(16) float sw[16 * 8];     // per-d packed (wpx,wpy,wpz,wdist,wmk,...)
    __shared__ unsigned stg[8 * 288];              // bf16 staging, stride 9 (conflict-free)
    __shared__ __align__(16) float res[8 * 640];   // f32 results, stride 20
    int tid = threadIdx.x;
    int lane = tid & 31, wid = tid >> 5;
    int g = lane >> 2, t = lane & 3;
    if (tid < 16) {
        sw[tid * 8 + 0] = W_pos[3 * tid];
        sw[tid * 8 + 1] = W_pos[3 * tid + 1];
        sw[tid * 8 + 2] = W_pos[3 * tid + 2];
        sw[tid * 8 + 3] = W_dist[tid];
        sw[tid * 8 + 4] = W_maskp[tid];
    }

    unsigned bf[3][4];
#pragma unroll
    for (int L = 0; L < 3; L++) {
        const float* W = (L == 0) ? W_m1 : (L == 1) ? W_m2 : W_m3;
        float2 w00 = *(const float2*)(W + g * 16 + 2 * t);
        float2 w01 = *(const float2*)(W + g * 16 + 2 * t + 8);
        float2 w10 = *(const float2*)(W + (g + 8) * 16 + 2 * t);
        float2 w11 = *(const float2*)(W + (g + 8) * 16 + 2 * t + 8);
        bf[L][0] = pkbf(w00.x, w00.y);
        bf[L][1] = pkbf(w01.x, w01.y);
        bf[L][2] = pkbf(w10.x, w10.y);
        bf[L][3] = pkbf(w11.x, w11.y);
    }
    __syncthreads();

    int gidx = blockIdx.x * 256 + tid;
    int hh = gidx & 127;
    int ww = (gidx >> 7) & 31;
    int kk = (gidx >> 12) & 127;
    int b  = gidx >> 19;
    int q = kk * 32 + ww;
    int bq = b * Nc + q;
    int key = kk * 32 + hh - 48;
    bool inr = (unsigned)key < (unsigned)Nc;
    int bk = b * Nc + (inr ? key : 0);

    float mq = amask[bq];
    float mk = inr ? amask[bk] : 0.f;
    int uq = uid[bq];
    int uk = uid[bk];
    float v = (mq != 0.f && mk != 0.f && uq == uk) ? 1.f : 0.f;

    float qx = ref_pos[bq * 3], qy = ref_pos[bq * 3 + 1], qz = ref_pos[bq * 3 + 2];
    float kx = 0.f, ky = 0.f, kz = 0.f;
    if (inr) { kx = ref_pos[bk * 3]; ky = ref_pos[bk * 3 + 1]; kz = ref_pos[bk * 3 + 2]; }
    float dx = kx - qx, dy = ky - qy, dz = kz - qz;
    float dn = 1.f / (1.f + dx * dx + dy * dy + dz * dz);

    float p[16];
#pragma unroll
    for (int d = 0; d < 16; d++) {
        float4 wv = *(const float4*)(sw + d * 8);
        float e = sw[d * 8 + 4];
        p[d] = v * (dx * wv.x + dy * wv.y + dz * wv.z + dn * wv.w + e);
    }
    {
        const float4* cq4 = (const float4*)(g_cq + (size_t)bq * 16);
#pragma unroll
        for (int i = 0; i < 4; i++) {
            float4 tt = cq4[i];
            p[4 * i] += tt.x; p[4 * i + 1] += tt.y; p[4 * i + 2] += tt.z; p[4 * i + 3] += tt.w;
        }
    }
    if (inr) {
        int tq = g_tok[bq];            // uniform per query (warp-broadcast)
        int bt = (b << 9) + tq;
        int lo = g_lo[bt];             // uniform
        int zoff = bt * CAP;
        int j = g_tok[bk] - lo;        // j >= 0 guaranteed by window construction
        if (j >= CAP) j = CAP - 1;     // overflow handled exactly by fixup_kernel
        const float4* zp4 = (const float4*)(g_z2pc + (size_t)(zoff + j) * 16);
        const float4* ck4 = (const float4*)(g_ck + (size_t)bk * 16);
#pragma unroll
        for (int i = 0; i < 4; i++) {
            float4 tt = zp4[i], u = ck4[i];
            p[4 * i]     += tt.x + u.x;
            p[4 * i + 1] += tt.y + u.y;
            p[4 * i + 2] += tt.z + u.z;
            p[4 * i + 3] += tt.w + u.w;
        }
    }

    // stage relu(p) as bf16 rows: [32 rows x 9 u32] per warp (stride 9 = conflict-free)
    unsigned* h2 = stg + wid * 288;
#pragma unroll
    for (int j2 = 0; j2 < 8; j2++)
        h2[lane * 9 + j2] = pkbf(fmaxf(p[2 * j2], 0.f), fmaxf(p[2 * j2 + 1], 0.f));
    __syncwarp();

    unsigned a0[2], a1[2], a2[2], a3[2];
#pragma unroll
    for (int tt = 0; tt < 2; tt++) {
        int rt = tt * 16;
        a0[tt] = h2[(rt + g) * 9 + t];
        a1[tt] = h2[(rt + g + 8) * 9 + t];
        a2[tt] = h2[(rt + g) * 9 + t + 4];
        a3[tt] = h2[(rt + g + 8) * 9 + t + 4];
    }
    __syncwarp();

    float* wsm = res + wid * 640;
#pragma unroll
    for (int tt = 0; tt < 2; tt++) {
        unsigned u0 = a0[tt], u1 = a1[tt], u2 = a2[tt], u3 = a3[tt];
        float dlo[4], dhi[4];
#pragma unroll
        for (int L = 0; L < 3; L++) {
            mma16816(dlo, u0, u1, u2, u3, bf[L][0], bf[L][1]);
            mma16816(dhi, u0, u1, u2, u3, bf[L][2], bf[L][3]);
            if (L < 2) {
                u0 = pkbf(fmaxf(dlo[0], 0.f), fmaxf(dlo[1], 0.f));
                u1 = pkbf(fmaxf(dlo[2], 0.f), fmaxf(dlo[3], 0.f));
                u2 = pkbf(fmaxf(dhi[0], 0.f), fmaxf(dhi[1], 0.f));
                u3 = pkbf(fmaxf(dhi[2], 0.f), fmaxf(dhi[3], 0.f));
            }
        }
        int r0 = tt * 16 + g, r1 = r0 + 8;
        *(float2*)(wsm + r0 * 20 + 2 * t)     = make_float2(dlo[0], dlo[1]);
        *(float2*)(wsm + r1 * 20 + 2 * t)     = make_float2(dlo[2], dlo[3]);
        *(float2*)(wsm + r0 * 20 + 8 + 2 * t) = make_float2(dhi[0], dhi[1]);
        *(float2*)(wsm + r1 * 20 + 8 + 2 * t) = make_float2(dhi[2], dhi[3]);
    }
    __syncwarp();

    float4* o4 = (float4*)(out + (size_t)gidx * 16);
    const float4* mrow = (const float4*)(wsm + lane * 20);
#pragma unroll
    for (int i = 0; i < 4; i++) {
        float4 mi = mrow[i];
        __stcs(o4 + i, make_float4(p[4 * i] + mi.x, p[4 * i + 1] + mi.y,
                                   p[4 * i + 2] + mi.z, p[4 * i + 3] + mi.w));
    }
}

// ---------------- fixup: exact recompute of window-overflow positions (rare) ----------
__global__ void fixup_kernel(
        const float* __restrict__ ref_pos, const float* __restrict__ amask,
        const int* __restrict__ uid, const float* __restrict__ z,
        const float* __restrict__ W_pos, const float* __restrict__ W_dist,
        const float* __restrict__ W_maskp,
        const float* __restrict__ W_m1, const float* __restrict__ W_m2,
        const float* __restrict__ W_m3,
        float* __restrict__ out) {
    if (!g_anyovf) return;
    int bt = blockIdx.x;                  // b*Tc + tq
    int amx = g_amax[bt];
    if (amx < 0) return;
    int amn = g_amin[bt];
    int b = bt >> 9;
    int alo = 32 * (amn >> 5) - 48; if (alo < 0) alo = 0;
    int ahi = 32 * (amx >> 5) + 79; if (ahi > Nc - 1) ahi = Nc - 1;
    int lo = g_tok[b * Nc + alo];
    int hi = g_tok[b * Nc + ahi];
    if (hi - lo < CAP) return;            // this tq was fully handled by main

    int hh = threadIdx.x;                 // 128 threads
    for (int q = amn; q <= amx; q++) {
        int kk = q >> 5;
        int key = kk * 32 + hh - 48;
        if ((unsigned)key >= (unsigned)Nc) continue;
        int bq = b * Nc + q;
        int bk = b * Nc + key;
        int tk2 = g_tok[bk];
        if (tk2 - lo < CAP) continue;     // main's value exact

        float mq = amask[bq], mk = amask[bk];
        float vv = (mq != 0.f && mk != 0.f && uid[bq] == uid[bk]) ? 1.f : 0.f;
        float dx = ref_pos[bk * 3] - ref_pos[bq * 3];
        float dy = ref_pos[bk * 3 + 1] - ref_pos[bq * 3 + 1];
        float dz = ref_pos[bk * 3 + 2] - ref_pos[bq * 3 + 2];
        float dn = 1.f / (1.f + dx * dx + dy * dy + dz * dz);

        const float* zrow = z + ((size_t)bt * Tc + tk2) * 128;
        float s = 0.f, s2 = 0.f;
        for (int f = 0; f < 128; f++) { float x = zrow[f]; s += x; s2 += x * x; }
        float mu = s * (1.f / 128.f);
        float rs = rsqrtf(s2 * (1.f / 128.f) - mu * mu + 1e-5f);

        float p[16];
        for (int d = 0; d < 16; d++) {
            float dot = 0.f;
            for (int f = 0; f < 128; f++) dot += zrow[f] * g_gw[d * 128 + f];
            float zc = rs * (dot - mu * g_gsum[d]) + g_bw[d];
            p[d] = vv * (dx * W_pos[3 * d] + dy * W_pos[3 * d + 1] + dz * W_pos[3 * d + 2]
                         + dn * W_dist[d] + W_maskp[d])
                   + g_cq[(size_t)bq * 16 + d] + g_ck[(size_t)bk * 16 + d] + zc;
        }
        float r0[16], r1[16], r2[16];
        for (int i = 0; i < 16; i++) {
            float a = 0.f;
            for (int j = 0; j < 16; j++) a += fmaxf(p[j], 0.f) * W_m1[i * 16 + j];
            r0[i] = a;
        }
        for (int i = 0; i < 16; i++) {
            float a = 0.f;
            for (int j = 0; j < 16; j++) a += fmaxf(r0[j], 0.f) * W_m2[i * 16 + j];
            r1[i] = a;
        }
        for (int i = 0; i < 16; i++) {
            float a = 0.f;
            for (int j = 0; j < 16; j++) a += fmaxf(r1[j], 0.f) * W_m3[i * 16 + j];
            r2[i] = a;
        }
        size_t gidx = ((size_t)b << 19) | ((size_t)kk << 12) | ((size_t)(q & 31) << 7) | hh;
        float* o = out + gidx * 16;
        for (int i = 0; i < 16; i++) o[i] = p[i] + r2[i];
    }
}

// ---------------- launch ----------------
extern "C" void kernel_launch(void* const* d_in, const int* in_sizes, int n_in,
                              void* d_out, int out_size) {
    const float* ref_pos             = (const float*)d_in[0];
    const float* ref_charge          = (const float*)d_in[1];
    const float* atom_pad_mask       = (const float*)d_in[2];
    const float* ref_element         = (const float*)d_in[3];
    const float* ref_atom_name_chars = (const float*)d_in[4];
    const int*   ref_space_uid       = (const int*)  d_in[5];
    const float* atom_to_token       = (const float*)d_in[6];
    const float* s_trunk             = (const float*)d_in[7];
    const float* z                   = (const float*)d_in[8];
    const float* W_feat              = (const float*)d_in[9];
    const float* W_pos               = (const float*)d_in[10];
    const float* W_dist              = (const float*)d_in[11];
    const float* W_maskp             = (const float*)d_in[12];
    const float* ln_s_g              = (const float*)d_in[13];
    const float* ln_s_b              = (const float*)d_in[14];
    const float* W_s2c               = (const float*)d_in[15];
    const float* ln_z_g              = (const float*)d_in[16];
    const float* ln_z_b              = (const float*)d_in[17];
    const float* W_z2p               = (const float*)d_in[18];
    const float* W_cq                = (const float*)d_in[19];
    const float* W_ck                = (const float*)d_in[20];
    const float* W_m1                = (const float*)d_in[21];
    const float* W_m2                = (const float*)d_in[22];
    const float* W_m3                = (const float*)d_in[23];
    float* out = (float*)d_out;

    prep_kernel<<<64, 256>>>(W_feat, W_s2c, W_z2p, ln_z_g, ln_z_b);
    tok_kernel<<<(Bc * Nc * 32) / 256, 256>>>(atom_to_token);
    s2c_kernel<<<Bc * Tc, 128>>>(s_trunk, ln_s_g, ln_s_b);
    c_kernel<<<(Bc * Nc) / 16, 256>>>(ref_pos, ref_charge, atom_pad_mask,
                                      ref_element, ref_atom_name_chars, W_cq, W_ck);
    z2pc_kernel<<<Bc * Tc, 256>>>(z);
    main_kernel<<<(Bc * 128 * 32 * 128) / 256, 256>>>(ref_pos, atom_pad_mask, ref_space_uid,
                                                      W_pos, W_dist, W_maskp,
                                                      W_m1, W_m2, W_m3, out);
    fixup_kernel<<<Bc * Tc, 128>>>(ref_pos, atom_pad_mask, ref_space_uid, z,
                                   W_pos, W_dist, W_maskp, W_m1, W_m2, W_m3, out);
}